// round 4
// baseline (speedup 1.0000x reference)
#include <cuda_runtime.h>
#include <cstdint>

#define D 128
#define S 12
#define KSTEPS 17          // K = 129 padded to 136, 8 per mma
#define LDF 136            // feat row stride (floats)
#define NT 16              // n-tiles of 8 -> N=128
#define MTILE 128          // rows per CTA tile
#define WARPS 4            // 32 rows per warp (2 x m16)

// ---- scratch (allocation-free rule) ----
__device__ float g_agg_a[3200  * 128];
__device__ float g_agg_b[38400 * 128];
__device__ float g_agg_c[3200  * 128];
__device__ float g_logits[460800];

// SMEM: feat[128][136] + bfrag[17*16*128] + w2s[128]
#define SMEM_FLOATS (MTILE * LDF + KSTEPS * NT * 128 + 128)
#define SMEM_BYTES  (SMEM_FLOATS * 4)

__device__ __forceinline__ uint32_t tf32_rna(float v) {
    uint32_t r; asm("cvt.rna.tf32.f32 %0, %1;" : "=r"(r) : "f"(v)); return r;
}
__device__ __forceinline__ void mma_tf32(float* d, const uint32_t* a, uint32_t b0, uint32_t b1) {
    asm volatile(
        "mma.sync.aligned.m16n8k8.row.col.f32.tf32.tf32.f32 "
        "{%0,%1,%2,%3}, {%4,%5,%6,%7}, {%8,%9}, {%0,%1,%2,%3};"
        : "+f"(d[0]), "+f"(d[1]), "+f"(d[2]), "+f"(d[3])
        : "r"(a[0]), "r"(a[1]), "r"(a[2]), "r"(a[3]), "r"(b0), "r"(b1));
}
__device__ __forceinline__ float lrelu(float x) { return x > 0.f ? x : 0.2f * x; }

// Phase A: logits[r] = lrelu( (item[r/12] (*) nbh[r] | nbw[r]) @ w1 ) @ w2
// Persistent CTAs; tf32 mma with hi/lo split (3 mma) for fp32-grade accuracy.
__global__ __launch_bounds__(128) void logits_kernel(
    const float* __restrict__ item, const float* __restrict__ nbh,
    const float* __restrict__ nbw,  const float* __restrict__ w1,
    const float* __restrict__ w2,   float* __restrict__ logits,
    int ntiles)
{
    extern __shared__ float sm[];
    float* feat = sm;                        // [128][136]
    float* bf   = sm + MTILE * LDF;          // [17][16][128] fragment-ordered
    float* w2s  = bf + KSTEPS * NT * 128;    // [128]

    const int tid  = threadIdx.x;
    const int lane = tid & 31;
    const int warp = tid >> 5;
    const int c = lane & 3;      // thread-in-group
    const int g = lane >> 2;     // group id
    const int wrow = warp * 32;

    // ---- one-time: stage w1 fragments (tf32 hi/lo), w2, zero feat pad ----
    // Fragment layout per (ks,j): 32 float4s, thread t gets {bhi(k=c), bhi(k=c+4), blo(k=c), blo(k=c+4)}, n=j*8+g
    for (int idx = tid; idx < KSTEPS * NT * 32; idx += 128) {
        int t  = idx & 31;
        int j  = (idx >> 5) & 15;
        int ks = idx >> 9;
        int tc = t & 3, tg = t >> 2;
        int k0 = ks * 8 + tc;
        int k1 = k0 + 4;
        int n  = j * 8 + tg;
        float v0 = (k0 < D + 1) ? w1[k0 * D + n] : 0.f;
        float v1 = (k1 < D + 1) ? w1[k1 * D + n] : 0.f;
        uint32_t h0 = tf32_rna(v0), h1 = tf32_rna(v1);
        uint32_t l0 = tf32_rna(v0 - __uint_as_float(h0));
        uint32_t l1 = tf32_rna(v1 - __uint_as_float(h1));
        float4* dst = (float4*)&bf[(size_t)idx * 4];
        *dst = make_float4(__uint_as_float(h0), __uint_as_float(h1),
                           __uint_as_float(l0), __uint_as_float(l1));
    }
    if (tid < D) w2s[tid] = w2[tid];
    for (int i = tid; i < MTILE * 8; i += 128) {       // zero cols 128..135
        int r = i >> 3, kk = 128 + (i & 7);
        feat[r * LDF + kk] = 0.f;
    }
    __syncthreads();

    const int rq = tid >> 5;          // 0..3 (reuse warp id)
    const int l32 = tid & 31;

    for (int tile = blockIdx.x; tile < ntiles; tile += gridDim.x) {
        const int rowbase = tile * MTILE;

        // ---- stage feat tile: feat[r][k] = item[R/12][k] * nbh[R][k]; col128 = nbw[R] ----
        for (int r0 = 0; r0 < MTILE; r0 += 4) {
            const int r = r0 + rq;
            const int R = rowbase + r;
            const int it = (unsigned)R / 12u;
            float4 a = ((const float4*)nbh)[(size_t)R * 32 + l32];
            float4 b = ((const float4*)item)[(size_t)it * 32 + l32];
            float4 f = make_float4(a.x * b.x, a.y * b.y, a.z * b.z, a.w * b.w);
            *(float4*)&feat[r * LDF + l32 * 4] = f;
            if (l32 == 0) feat[r * LDF + 128] = nbw[R];
        }
        __syncthreads();

        // ---- mainloop ----
        float acc[2][NT][4];
        #pragma unroll
        for (int a = 0; a < 2; a++)
            #pragma unroll
            for (int j = 0; j < NT; j++)
                #pragma unroll
                for (int q = 0; q < 4; q++) acc[a][j][q] = 0.f;

        #pragma unroll 1
        for (int ks = 0; ks < KSTEPS; ks++) {
            const int k0 = ks * 8;
            // A fragments: rows {g,g+8}, cols {c, c+4} per m16 tile; split hi/lo
            uint32_t ahi[2][4], alo[2][4];
            #pragma unroll
            for (int a = 0; a < 2; a++) {
                const float* fr  = &feat[(wrow + a * 16 + g) * LDF + k0];
                const float* fr8 = fr + 8 * LDF;
                float f0 = fr[c], f1 = fr8[c], f2 = fr[c + 4], f3 = fr8[c + 4];
                ahi[a][0] = tf32_rna(f0); alo[a][0] = tf32_rna(f0 - __uint_as_float(ahi[a][0]));
                ahi[a][1] = tf32_rna(f1); alo[a][1] = tf32_rna(f1 - __uint_as_float(ahi[a][1]));
                ahi[a][2] = tf32_rna(f2); alo[a][2] = tf32_rna(f2 - __uint_as_float(ahi[a][2]));
                ahi[a][3] = tf32_rna(f3); alo[a][3] = tf32_rna(f3 - __uint_as_float(ahi[a][3]));
            }
            const float4* bks = (const float4*)&bf[(size_t)ks * NT * 128];
            #pragma unroll
            for (int j = 0; j < NT; j++) {
                float4 bq = bks[j * 32 + lane];          // one conflict-free LDS.128
                uint32_t bh0 = __float_as_uint(bq.x), bh1 = __float_as_uint(bq.y);
                uint32_t bl0 = __float_as_uint(bq.z), bl1 = __float_as_uint(bq.w);
                #pragma unroll
                for (int a = 0; a < 2; a++) {
                    mma_tf32(acc[a][j], ahi[a], bh0, bh1);
                    mma_tf32(acc[a][j], alo[a], bh0, bh1);
                    mma_tf32(acc[a][j], ahi[a], bl0, bl1);
                }
            }
        }

        // ---- epilogue: logit[row] = sum_n lrelu(O[row,n]) * w2[n] ----
        #pragma unroll
        for (int a = 0; a < 2; a++) {
            float l0 = 0.f, l1 = 0.f;
            #pragma unroll
            for (int j = 0; j < NT; j++) {
                float2 wv = *(const float2*)&w2s[j * 8 + 2 * c];
                l0 = fmaf(lrelu(acc[a][j][0]), wv.x, l0);
                l0 = fmaf(lrelu(acc[a][j][1]), wv.y, l0);
                l1 = fmaf(lrelu(acc[a][j][2]), wv.x, l1);
                l1 = fmaf(lrelu(acc[a][j][3]), wv.y, l1);
            }
            l0 += __shfl_xor_sync(0xffffffffu, l0, 1);
            l0 += __shfl_xor_sync(0xffffffffu, l0, 2);
            l1 += __shfl_xor_sync(0xffffffffu, l1, 1);
            l1 += __shfl_xor_sync(0xffffffffu, l1, 2);
            if (c == 0) {
                const int R = rowbase + wrow + a * 16 + g;
                logits[R]     = l0;
                logits[R + 8] = l1;
            }
        }
        __syncthreads();   // feat reused next tile
    }
}

// Phase B: warp per item — softmax over 12 logits, weighted sum of neighbors.
__global__ __launch_bounds__(256) void aggout_kernel(
    const float* __restrict__ logits, const float* __restrict__ nbh,
    float* __restrict__ out, int nitems)
{
    const int lane = threadIdx.x & 31;
    const int warp = threadIdx.x >> 5;
    const int n = blockIdx.x * 8 + warp;
    if (n >= nitems) return;

    float lg[S];
    #pragma unroll
    for (int s = 0; s < S; s++) lg[s] = __ldg(&logits[n * S + s]);
    float m = lg[0];
    #pragma unroll
    for (int s = 1; s < S; s++) m = fmaxf(m, lg[s]);
    float e[S]; float sum = 0.f;
    #pragma unroll
    for (int s = 0; s < S; s++) { e[s] = __expf(lg[s] - m); sum += e[s]; }
    const float inv = 1.f / sum;

    const float* nb = nbh + (size_t)n * S * D;
    #pragma unroll
    for (int j = 0; j < 4; j++) {
        const int col = lane + 32 * j;
        float o = 0.f;
        #pragma unroll
        for (int s = 0; s < S; s++) o = fmaf(e[s] * inv, nb[s * D + col], o);
        out[(size_t)n * D + col] = o;
    }
}

// ---- final gating (R2 shape: block per item, 128 threads) ----
#define FMA2(acc, a, b) \
    asm("fma.rn.f32x2 %0, %1, %2, %0;" : "+l"(acc) : "l"(a), "l"(b))
__device__ __forceinline__ unsigned long long pack_f32(float lo, float hi) {
    unsigned long long p;
    asm("mov.b64 %0, {%1, %2};" : "=l"(p) : "r"(__float_as_uint(lo)), "r"(__float_as_uint(hi)));
    return p;
}
__device__ __forceinline__ void unpack_f32(unsigned long long p, float& lo, float& hi) {
    asm("mov.b64 {%0, %1}, %2;" : "=f"(lo), "=f"(hi) : "l"(p));
}

__global__ __launch_bounds__(128) void final_kernel(
    const float* __restrict__ hidden, const float* __restrict__ agg_a,
    const float* __restrict__ agg_c,  const float* __restrict__ w3,
    const float* __restrict__ w4,     const float* __restrict__ sv,
    float* __restrict__ out)
{
    const int n = blockIdx.x;
    const int t = threadIdx.x;
    __shared__ unsigned long long sh_hg[D];

    const float s0 = sv[0], s1 = sv[1];
    float h = hidden[(size_t)n * D + t];
    float g = s0 * agg_a[(size_t)n * D + t] + s1 * agg_c[(size_t)n * D + t];
    sh_hg[t] = pack_f32(h, g);
    __syncthreads();

    unsigned long long acc = 0;
    const float* w3c = w3 + t;
    const float* w4c = w4 + t;
    #pragma unroll 4
    for (int k = 0; k < D; k++) {
        unsigned long long wp = pack_f32(__ldg(&w3c[k * D]), __ldg(&w4c[k * D]));
        FMA2(acc, sh_hg[k], wp);
    }
    float a0, a1;
    unpack_f32(acc, a0, a1);
    float wgt = 1.f / (1.f + __expf(-(a0 + a1)));
    out[(size_t)n * D + t] = (1.f - wgt) * h + wgt * g;
}

extern "C" void kernel_launch(void* const* d_in, const int* in_sizes, int n_in,
                              void* d_out, int out_size)
{
    const float* hidden = (const float*)d_in[0];
    const float* nh1    = (const float*)d_in[1];
    const float* nh2    = (const float*)d_in[2];
    const float* nw0    = (const float*)d_in[3];
    const float* nw1    = (const float*)d_in[4];
    const float* w1     = (const float*)d_in[5];
    const float* w2     = (const float*)d_in[6];
    const float* w3     = (const float*)d_in[7];
    const float* w4     = (const float*)d_in[8];
    const float* sv     = (const float*)d_in[9];
    float* out = (float*)d_out;

    float *agg_a, *agg_b, *agg_c, *logits;
    cudaGetSymbolAddress((void**)&agg_a,  g_agg_a);
    cudaGetSymbolAddress((void**)&agg_b,  g_agg_b);
    cudaGetSymbolAddress((void**)&agg_c,  g_agg_c);
    cudaGetSymbolAddress((void**)&logits, g_logits);

    cudaFuncSetAttribute(logits_kernel,
                         cudaFuncAttributeMaxDynamicSharedMemorySize, SMEM_BYTES);

    const int GP = 148;                 // persistent grid
    const int T0 = 38400  / MTILE;      // 300 tiles (3200 items)
    const int T1 = 460800 / MTILE;      // 3600 tiles (38400 items)

    // hop 1, level 0
    logits_kernel<<<GP, 128, SMEM_BYTES>>>(hidden, nh1, nw0, w1, w2, logits, T0);
    aggout_kernel<<<400, 256>>>(logits, nh1, agg_a, 3200);
    // hop 1, level 1
    logits_kernel<<<GP, 128, SMEM_BYTES>>>(nh1, nh2, nw1, w1, w2, logits, T1);
    aggout_kernel<<<4800, 256>>>(logits, nh2, agg_b, 38400);
    // hop 2
    logits_kernel<<<GP, 128, SMEM_BYTES>>>(agg_a, agg_b, nw0, w1, w2, logits, T0);
    aggout_kernel<<<400, 256>>>(logits, agg_b, agg_c, 3200);
    // gate
    final_kernel<<<3200, 128>>>(hidden, agg_a, agg_c, w3, w4, sv, out);
}

// round 5
// speedup vs baseline: 1.5158x; 1.5158x over previous
#include <cuda_runtime.h>
#include <cstdint>

#define D 128
#define S 12
#define KSTEPS 17          // K = 129 padded to 136, 8 per mma
#define LDF 140            // feat row stride (floats) -> conflict-free A reads
#define NT 16              // n-tiles of 8 -> N=128
#define MTILE 128          // rows per CTA tile
#define NWARPS 8           // 16 rows per warp (one m16 tile)

// ---- scratch (allocation-free rule) ----
__device__ float g_agg_a[3200  * 128];
__device__ float g_agg_b[38400 * 128];
__device__ float g_agg_c[3200  * 128];
__device__ float g_logits[460800];

// SMEM: feat[128][140] + bfrag[17*16*32*4] + w2s[128]  = 206.5 KB
#define BTAB_FLOATS (KSTEPS * NT * 32 * 4)
#define SMEM_FLOATS (MTILE * LDF + BTAB_FLOATS + 128)
#define SMEM_BYTES  (SMEM_FLOATS * 4)

__device__ __forceinline__ uint32_t tf32_rna(float v) {
    uint32_t r; asm("cvt.rna.tf32.f32 %0, %1;" : "=r"(r) : "f"(v)); return r;
}
__device__ __forceinline__ void mma_tf32(float* d, const uint32_t* a, uint32_t b0, uint32_t b1) {
    asm volatile(
        "mma.sync.aligned.m16n8k8.row.col.f32.tf32.tf32.f32 "
        "{%0,%1,%2,%3}, {%4,%5,%6,%7}, {%8,%9}, {%0,%1,%2,%3};"
        : "+f"(d[0]), "+f"(d[1]), "+f"(d[2]), "+f"(d[3])
        : "r"(a[0]), "r"(a[1]), "r"(a[2]), "r"(a[3]), "r"(b0), "r"(b1));
}
__device__ __forceinline__ float lrelu(float x) { return x > 0.f ? x : 0.2f * x; }

// Phase A: logits[r] = lrelu( (item[r/12] (*) nbh[r] | nbw[r]) @ w1 ) @ w2
// Persistent CTAs, 8 warps; tf32 mma, 3-term hi/lo split (fp32-grade accuracy).
__global__ __launch_bounds__(256, 1) void logits_kernel(
    const float* __restrict__ item, const float* __restrict__ nbh,
    const float* __restrict__ nbw,  const float* __restrict__ w1,
    const float* __restrict__ w2,   float* __restrict__ logits,
    int ntiles)
{
    extern __shared__ float sm[];
    float* feat = sm;                        // [128][140]
    float* bf   = sm + MTILE * LDF;          // [17][16][32][4] fragment-ordered
    float* w2s  = bf + BTAB_FLOATS;          // [128]

    const int tid  = threadIdx.x;
    const int lane = tid & 31;
    const int warp = tid >> 5;
    const int c = lane & 3;      // thread col-in-group (k)
    const int g = lane >> 2;     // group id (row / n)
    const int wrow = warp * 16;  // 16 rows per warp

    // ---- one-time: stage w1 fragments (tf32 hi/lo), w2 ----
    // per (ks,j): thread t holds float4 {bhi(k0), bhi(k1), blo(k0), blo(k1)}, n=j*8+g
    for (int idx = tid; idx < KSTEPS * NT * 32; idx += 256) {
        int t  = idx & 31;
        int j  = (idx >> 5) & 15;
        int ks = idx >> 9;
        int tc = t & 3, tg = t >> 2;
        int k0 = ks * 8 + tc;
        int k1 = k0 + 4;
        int n  = j * 8 + tg;
        float v0 = (k0 < D + 1) ? w1[k0 * D + n] : 0.f;
        float v1 = (k1 < D + 1) ? w1[k1 * D + n] : 0.f;
        uint32_t h0 = tf32_rna(v0), h1 = tf32_rna(v1);
        uint32_t l0 = tf32_rna(v0 - __uint_as_float(h0));
        uint32_t l1 = tf32_rna(v1 - __uint_as_float(h1));
        *(float4*)&bf[(size_t)idx * 4] =
            make_float4(__uint_as_float(h0), __uint_as_float(h1),
                        __uint_as_float(l0), __uint_as_float(l1));
    }
    if (tid < D) w2s[tid] = w2[tid];
    __syncthreads();

    for (int tile = blockIdx.x; tile < ntiles; tile += gridDim.x) {
        const int rowbase = tile * MTILE;

        // ---- stage feat tile: feat[r][k] = item[R/12][k] * nbh[R][k]; col128 = nbw ----
        #pragma unroll
        for (int r0 = 0; r0 < MTILE; r0 += NWARPS) {
            const int r = r0 + warp;
            const int R = rowbase + r;
            const int it = (unsigned)R / 12u;
            float4 a = ((const float4*)nbh)[(size_t)R * 32 + lane];
            float4 b = ((const float4*)item)[(size_t)it * 32 + lane];
            *(float4*)&feat[r * LDF + lane * 4] =
                make_float4(a.x * b.x, a.y * b.y, a.z * b.z, a.w * b.w);
        }
        if (tid < MTILE) {
            float* fr = &feat[tid * LDF];
            fr[128] = nbw[rowbase + tid];
            #pragma unroll
            for (int kk = 129; kk < 136; kk++) fr[kk] = 0.f;
        }
        __syncthreads();

        // ---- mainloop: one m16 tile (16 rows) per warp, N=128 ----
        float acc[NT][4];
        #pragma unroll
        for (int j = 0; j < NT; j++)
            #pragma unroll
            for (int q = 0; q < 4; q++) acc[j][q] = 0.f;

        #pragma unroll 1
        for (int ks = 0; ks < KSTEPS; ks++) {
            const int k0 = ks * 8;
            // A fragment: rows {g, g+8}, cols {c, c+4}; split hi/lo
            uint32_t ahi[4], alo[4];
            {
                const float* fr  = &feat[(wrow + g) * LDF + k0];
                const float* fr8 = fr + 8 * LDF;
                float f0 = fr[c], f1 = fr8[c], f2 = fr[c + 4], f3 = fr8[c + 4];
                ahi[0] = tf32_rna(f0); alo[0] = tf32_rna(f0 - __uint_as_float(ahi[0]));
                ahi[1] = tf32_rna(f1); alo[1] = tf32_rna(f1 - __uint_as_float(ahi[1]));
                ahi[2] = tf32_rna(f2); alo[2] = tf32_rna(f2 - __uint_as_float(ahi[2]));
                ahi[3] = tf32_rna(f3); alo[3] = tf32_rna(f3 - __uint_as_float(ahi[3]));
            }
            const float4* bks = (const float4*)&bf[(size_t)ks * NT * 128];
            #pragma unroll
            for (int j = 0; j < NT; j++) {
                float4 bq = bks[j * 32 + lane];          // conflict-free LDS.128
                uint32_t bh0 = __float_as_uint(bq.x), bh1 = __float_as_uint(bq.y);
                uint32_t bl0 = __float_as_uint(bq.z), bl1 = __float_as_uint(bq.w);
                mma_tf32(acc[j], ahi, bh0, bh1);
                mma_tf32(acc[j], alo, bh0, bh1);
                mma_tf32(acc[j], ahi, bl0, bl1);
            }
        }

        // ---- epilogue: logit[row] = sum_n lrelu(O[row,n]) * w2[n] ----
        {
            float l0 = 0.f, l1 = 0.f;
            #pragma unroll
            for (int j = 0; j < NT; j++) {
                float2 wv = *(const float2*)&w2s[j * 8 + 2 * c];
                l0 = fmaf(lrelu(acc[j][0]), wv.x, l0);
                l0 = fmaf(lrelu(acc[j][1]), wv.y, l0);
                l1 = fmaf(lrelu(acc[j][2]), wv.x, l1);
                l1 = fmaf(lrelu(acc[j][3]), wv.y, l1);
            }
            l0 += __shfl_xor_sync(0xffffffffu, l0, 1);
            l0 += __shfl_xor_sync(0xffffffffu, l0, 2);
            l1 += __shfl_xor_sync(0xffffffffu, l1, 1);
            l1 += __shfl_xor_sync(0xffffffffu, l1, 2);
            if (c == 0) {
                const int R = rowbase + wrow + g;
                logits[R]     = l0;
                logits[R + 8] = l1;
            }
        }
        __syncthreads();   // feat reused next tile
    }
}

// Phase B: warp per item — softmax over 12 logits, weighted sum of neighbors.
__global__ __launch_bounds__(256) void aggout_kernel(
    const float* __restrict__ logits, const float* __restrict__ nbh,
    float* __restrict__ out, int nitems)
{
    const int lane = threadIdx.x & 31;
    const int warp = threadIdx.x >> 5;
    const int n = blockIdx.x * 8 + warp;
    if (n >= nitems) return;

    float lg[S];
    #pragma unroll
    for (int s = 0; s < S; s++) lg[s] = __ldg(&logits[n * S + s]);
    float m = lg[0];
    #pragma unroll
    for (int s = 1; s < S; s++) m = fmaxf(m, lg[s]);
    float e[S]; float sum = 0.f;
    #pragma unroll
    for (int s = 0; s < S; s++) { e[s] = __expf(lg[s] - m); sum += e[s]; }
    const float inv = 1.f / sum;

    const float* nb = nbh + (size_t)n * S * D;
    #pragma unroll
    for (int j = 0; j < 4; j++) {
        const int col = lane + 32 * j;
        float o = 0.f;
        #pragma unroll
        for (int s = 0; s < S; s++) o = fmaf(e[s] * inv, nb[s * D + col], o);
        out[(size_t)n * D + col] = o;
    }
}

// ---- final gating (block per item, 128 threads; FFMA2-packed dual GEMV) ----
#define FMA2(acc, a, b) \
    asm("fma.rn.f32x2 %0, %1, %2, %0;" : "+l"(acc) : "l"(a), "l"(b))
__device__ __forceinline__ unsigned long long pack_f32(float lo, float hi) {
    unsigned long long p;
    asm("mov.b64 %0, {%1, %2};" : "=l"(p) : "r"(__float_as_uint(lo)), "r"(__float_as_uint(hi)));
    return p;
}
__device__ __forceinline__ void unpack_f32(unsigned long long p, float& lo, float& hi) {
    asm("mov.b64 {%0, %1}, %2;" : "=f"(lo), "=f"(hi) : "l"(p));
}

__global__ __launch_bounds__(128) void final_kernel(
    const float* __restrict__ hidden, const float* __restrict__ agg_a,
    const float* __restrict__ agg_c,  const float* __restrict__ w3,
    const float* __restrict__ w4,     const float* __restrict__ sv,
    float* __restrict__ out)
{
    const int n = blockIdx.x;
    const int t = threadIdx.x;
    __shared__ unsigned long long sh_hg[D];

    const float s0 = sv[0], s1 = sv[1];
    float h = hidden[(size_t)n * D + t];
    float g = s0 * agg_a[(size_t)n * D + t] + s1 * agg_c[(size_t)n * D + t];
    sh_hg[t] = pack_f32(h, g);
    __syncthreads();

    unsigned long long acc = 0;
    const float* w3c = w3 + t;
    const float* w4c = w4 + t;
    #pragma unroll 4
    for (int k = 0; k < D; k++) {
        unsigned long long wp = pack_f32(__ldg(&w3c[k * D]), __ldg(&w4c[k * D]));
        FMA2(acc, sh_hg[k], wp);
    }
    float a0, a1;
    unpack_f32(acc, a0, a1);
    float wgt = 1.f / (1.f + __expf(-(a0 + a1)));
    out[(size_t)n * D + t] = (1.f - wgt) * h + wgt * g;
}

extern "C" void kernel_launch(void* const* d_in, const int* in_sizes, int n_in,
                              void* d_out, int out_size)
{
    const float* hidden = (const float*)d_in[0];
    const float* nh1    = (const float*)d_in[1];
    const float* nh2    = (const float*)d_in[2];
    const float* nw0    = (const float*)d_in[3];
    const float* nw1    = (const float*)d_in[4];
    const float* w1     = (const float*)d_in[5];
    const float* w2     = (const float*)d_in[6];
    const float* w3     = (const float*)d_in[7];
    const float* w4     = (const float*)d_in[8];
    const float* sv     = (const float*)d_in[9];
    float* out = (float*)d_out;

    float *agg_a, *agg_b, *agg_c, *logits;
    cudaGetSymbolAddress((void**)&agg_a,  g_agg_a);
    cudaGetSymbolAddress((void**)&agg_b,  g_agg_b);
    cudaGetSymbolAddress((void**)&agg_c,  g_agg_c);
    cudaGetSymbolAddress((void**)&logits, g_logits);

    cudaFuncSetAttribute(logits_kernel,
                         cudaFuncAttributeMaxDynamicSharedMemorySize, SMEM_BYTES);

    const int GP = 148;                 // persistent grid
    const int T0 = 38400  / MTILE;      // 300 tiles (3200 items)
    const int T1 = 460800 / MTILE;      // 3600 tiles (38400 items)

    // hop 1, level 0
    logits_kernel<<<GP, 256, SMEM_BYTES>>>(hidden, nh1, nw0, w1, w2, logits, T0);
    aggout_kernel<<<400, 256>>>(logits, nh1, agg_a, 3200);
    // hop 1, level 1
    logits_kernel<<<GP, 256, SMEM_BYTES>>>(nh1, nh2, nw1, w1, w2, logits, T1);
    aggout_kernel<<<4800, 256>>>(logits, nh2, agg_b, 38400);
    // hop 2
    logits_kernel<<<GP, 256, SMEM_BYTES>>>(agg_a, agg_b, nw0, w1, w2, logits, T0);
    aggout_kernel<<<400, 256>>>(logits, agg_b, agg_c, 3200);
    // gate
    final_kernel<<<3200, 128>>>(hidden, agg_a, agg_c, w3, w4, sv, out);
}

// round 6
// speedup vs baseline: 2.3726x; 1.5653x over previous
#include <cuda_runtime.h>
#include <cstdint>

#define D 128
#define S 12
#define KSTEPS 16          // K = 128, 8 per mma; bias row handled in epilogue
#define LDF 132            // feat row stride (floats) -> conflict-free A reads
#define NT 16              // n-tiles of 8 -> N=128
#define MTILE 256          // rows per CTA tile
#define NWARPS 16          // 16 rows per warp (one m16 tile)

// ---- scratch (allocation-free rule) ----
__device__ float g_agg_a[3200  * 128];
__device__ float g_agg_b[38400 * 128];
__device__ float g_agg_c[3200  * 128];
__device__ float g_logits[460800];

// SMEM: feat[256][132] + bfrag[16*16*32*2] + w1b[128] + w2s[128] + nbws[256]
#define BTAB_FLOATS (KSTEPS * NT * 32 * 2)
#define SMEM_FLOATS (MTILE * LDF + BTAB_FLOATS + 128 + 128 + MTILE)
#define SMEM_BYTES  (SMEM_FLOATS * 4)

__device__ __forceinline__ uint32_t tf32_rna(float v) {
    uint32_t r; asm("cvt.rna.tf32.f32 %0, %1;" : "=r"(r) : "f"(v)); return r;
}
__device__ __forceinline__ void mma_tf32(float* d, const uint32_t* a, uint32_t b0, uint32_t b1) {
    asm volatile(
        "mma.sync.aligned.m16n8k8.row.col.f32.tf32.tf32.f32 "
        "{%0,%1,%2,%3}, {%4,%5,%6,%7}, {%8,%9}, {%0,%1,%2,%3};"
        : "+f"(d[0]), "+f"(d[1]), "+f"(d[2]), "+f"(d[3])
        : "r"(a[0]), "r"(a[1]), "r"(a[2]), "r"(a[3]), "r"(b0), "r"(b1));
}
__device__ __forceinline__ float lrelu(float x) { return x > 0.f ? x : 0.2f * x; }

// Phase A: logits[r] = lrelu( (item[r/12] (*) nbh[r] | nbw[r]) @ w1 ) @ w2
// Persistent CTAs, 16 warps, MTILE=256; single tf32 mma per fragment.
__global__ __launch_bounds__(512, 1) void logits_kernel(
    const float* __restrict__ item, const float* __restrict__ nbh,
    const float* __restrict__ nbw,  const float* __restrict__ w1,
    const float* __restrict__ w2,   float* __restrict__ logits,
    int ntiles)
{
    extern __shared__ float sm[];
    float* feat = sm;                        // [256][132]
    float* bf   = sm + MTILE * LDF;          // [16][16][32] float2 fragment table
    float* w1b  = bf + BTAB_FLOATS;          // [128]  bias row w1[128][:]
    float* w2s  = w1b + 128;                 // [128]
    float* nbws = w2s + 128;                 // [256]

    const int tid  = threadIdx.x;
    const int lane = tid & 31;
    const int warp = tid >> 5;
    const int c = lane & 3;      // thread col-in-group (k / out-col pair)
    const int g = lane >> 2;     // group id (row)
    const int wrow = warp * 16;

    // ---- one-time: stage w1 fragment table (tf32), w1 bias row, w2 ----
    // per (ks,j): thread t holds float2 {b(k0), b(k1)} tf32-rounded, n=j*8+(t>>2)
    for (int idx = tid; idx < KSTEPS * NT * 32; idx += 512) {
        int t  = idx & 31;
        int j  = (idx >> 5) & 15;
        int ks = idx >> 9;
        int tc = t & 3, tg = t >> 2;
        int k0 = ks * 8 + tc;
        int n  = j * 8 + tg;
        float v0 = w1[k0 * D + n];
        float v1 = w1[(k0 + 4) * D + n];
        *(float2*)&bf[(size_t)idx * 2] =
            make_float2(__uint_as_float(tf32_rna(v0)), __uint_as_float(tf32_rna(v1)));
    }
    if (tid < D) { w1b[tid] = w1[D * D + tid]; w2s[tid] = w2[tid]; }
    __syncthreads();

    for (int tile = blockIdx.x; tile < ntiles; tile += gridDim.x) {
        const int rowbase = tile * MTILE;

        // ---- stage feat tile: feat[r][k] = item[R/12][k] * nbh[R][k] ----
        #pragma unroll
        for (int i = 0; i < (MTILE * 32) / 512; i++) {   // 16 iters
            const int idx = tid + i * 512;
            const int r = idx >> 5, l4 = idx & 31;
            const int R = rowbase + r;
            const int it = (unsigned)R / 12u;
            float4 a = ((const float4*)nbh)[(size_t)R * 32 + l4];
            float4 b = ((const float4*)item)[(size_t)it * 32 + l4];
            *(float4*)&feat[r * LDF + l4 * 4] =
                make_float4(a.x * b.x, a.y * b.y, a.z * b.z, a.w * b.w);
        }
        if (tid < MTILE) nbws[tid] = nbw[rowbase + tid];
        __syncthreads();

        // ---- mainloop: one m16 tile (16 rows) per warp, N=128 ----
        float acc[NT][4];
        #pragma unroll
        for (int j = 0; j < NT; j++)
            #pragma unroll
            for (int q = 0; q < 4; q++) acc[j][q] = 0.f;

        #pragma unroll 1
        for (int ks = 0; ks < KSTEPS; ks++) {
            const int k0 = ks * 8;
            uint32_t a[4];
            {
                const float* fr  = &feat[(wrow + g) * LDF + k0];
                const float* fr8 = fr + 8 * LDF;
                a[0] = tf32_rna(fr[c]);
                a[1] = tf32_rna(fr8[c]);
                a[2] = tf32_rna(fr[c + 4]);
                a[3] = tf32_rna(fr8[c + 4]);
            }
            const float2* bks = (const float2*)&bf[(size_t)ks * NT * 64];
            #pragma unroll
            for (int j = 0; j < NT; j++) {
                float2 bq = bks[j * 32 + lane];          // conflict-free LDS.64
                mma_tf32(acc[j], a, __float_as_uint(bq.x), __float_as_uint(bq.y));
            }
        }

        // ---- epilogue: add bias term, lrelu, dot w2, reduce over c ----
        {
            const float nbw0 = nbws[wrow + g];
            const float nbw1 = nbws[wrow + g + 8];
            float l0 = 0.f, l1 = 0.f;
            #pragma unroll
            for (int j = 0; j < NT; j++) {
                float2 wb = *(const float2*)&w1b[j * 8 + 2 * c];
                float2 wv = *(const float2*)&w2s[j * 8 + 2 * c];
                float v0 = fmaf(nbw0, wb.x, acc[j][0]);
                float v1 = fmaf(nbw0, wb.y, acc[j][1]);
                float v2 = fmaf(nbw1, wb.x, acc[j][2]);
                float v3 = fmaf(nbw1, wb.y, acc[j][3]);
                l0 = fmaf(lrelu(v0), wv.x, l0);
                l0 = fmaf(lrelu(v1), wv.y, l0);
                l1 = fmaf(lrelu(v2), wv.x, l1);
                l1 = fmaf(lrelu(v3), wv.y, l1);
            }
            l0 += __shfl_xor_sync(0xffffffffu, l0, 1);
            l0 += __shfl_xor_sync(0xffffffffu, l0, 2);
            l1 += __shfl_xor_sync(0xffffffffu, l1, 1);
            l1 += __shfl_xor_sync(0xffffffffu, l1, 2);
            if (c == 0) {
                const int R = rowbase + wrow + g;
                logits[R]     = l0;
                logits[R + 8] = l1;
            }
        }
        __syncthreads();   // feat reused next tile
    }
}

// Phase B: warp per item — softmax over 12 logits, weighted sum of neighbors.
__global__ __launch_bounds__(256) void aggout_kernel(
    const float* __restrict__ logits, const float* __restrict__ nbh,
    float* __restrict__ out, int nitems)
{
    const int lane = threadIdx.x & 31;
    const int warp = threadIdx.x >> 5;
    const int n = blockIdx.x * 8 + warp;
    if (n >= nitems) return;

    float lg[S];
    #pragma unroll
    for (int s = 0; s < S; s++) lg[s] = __ldg(&logits[n * S + s]);
    float m = lg[0];
    #pragma unroll
    for (int s = 1; s < S; s++) m = fmaxf(m, lg[s]);
    float e[S]; float sum = 0.f;
    #pragma unroll
    for (int s = 0; s < S; s++) { e[s] = __expf(lg[s] - m); sum += e[s]; }
    const float inv = 1.f / sum;

    const float* nb = nbh + (size_t)n * S * D;
    #pragma unroll
    for (int j = 0; j < 4; j++) {
        const int col = lane + 32 * j;
        float o = 0.f;
        #pragma unroll
        for (int s = 0; s < S; s++) o = fmaf(e[s] * inv, nb[s * D + col], o);
        out[(size_t)n * D + col] = o;
    }
}

// ---- final gating (block per item, 128 threads; FFMA2-packed dual GEMV) ----
#define FMA2(acc, a, b) \
    asm("fma.rn.f32x2 %0, %1, %2, %0;" : "+l"(acc) : "l"(a), "l"(b))
__device__ __forceinline__ unsigned long long pack_f32(float lo, float hi) {
    unsigned long long p;
    asm("mov.b64 %0, {%1, %2};" : "=l"(p) : "r"(__float_as_uint(lo)), "r"(__float_as_uint(hi)));
    return p;
}
__device__ __forceinline__ void unpack_f32(unsigned long long p, float& lo, float& hi) {
    asm("mov.b64 {%0, %1}, %2;" : "=f"(lo), "=f"(hi) : "l"(p));
}

__global__ __launch_bounds__(128) void final_kernel(
    const float* __restrict__ hidden, const float* __restrict__ agg_a,
    const float* __restrict__ agg_c,  const float* __restrict__ w3,
    const float* __restrict__ w4,     const float* __restrict__ sv,
    float* __restrict__ out)
{
    const int n = blockIdx.x;
    const int t = threadIdx.x;
    __shared__ unsigned long long sh_hg[D];

    const float s0 = sv[0], s1 = sv[1];
    float h = hidden[(size_t)n * D + t];
    float g = s0 * agg_a[(size_t)n * D + t] + s1 * agg_c[(size_t)n * D + t];
    sh_hg[t] = pack_f32(h, g);
    __syncthreads();

    unsigned long long acc = 0;
    const float* w3c = w3 + t;
    const float* w4c = w4 + t;
    #pragma unroll 4
    for (int k = 0; k < D; k++) {
        unsigned long long wp = pack_f32(__ldg(&w3c[k * D]), __ldg(&w4c[k * D]));
        FMA2(acc, sh_hg[k], wp);
    }
    float a0, a1;
    unpack_f32(acc, a0, a1);
    float wgt = 1.f / (1.f + __expf(-(a0 + a1)));
    out[(size_t)n * D + t] = (1.f - wgt) * h + wgt * g;
}

extern "C" void kernel_launch(void* const* d_in, const int* in_sizes, int n_in,
                              void* d_out, int out_size)
{
    const float* hidden = (const float*)d_in[0];
    const float* nh1    = (const float*)d_in[1];
    const float* nh2    = (const float*)d_in[2];
    const float* nw0    = (const float*)d_in[3];
    const float* nw1    = (const float*)d_in[4];
    const float* w1     = (const float*)d_in[5];
    const float* w2     = (const float*)d_in[6];
    const float* w3     = (const float*)d_in[7];
    const float* w4     = (const float*)d_in[8];
    const float* sv     = (const float*)d_in[9];
    float* out = (float*)d_out;

    float *agg_a, *agg_b, *agg_c, *logits;
    cudaGetSymbolAddress((void**)&agg_a,  g_agg_a);
    cudaGetSymbolAddress((void**)&agg_b,  g_agg_b);
    cudaGetSymbolAddress((void**)&agg_c,  g_agg_c);
    cudaGetSymbolAddress((void**)&logits, g_logits);

    cudaFuncSetAttribute(logits_kernel,
                         cudaFuncAttributeMaxDynamicSharedMemorySize, SMEM_BYTES);

    const int GP = 148;                 // persistent grid
    const int T0 = 38400  / MTILE;      // 150 tiles (3200 items)
    const int T1 = 460800 / MTILE;      // 1800 tiles (38400 items)

    // hop 1, level 0
    logits_kernel<<<GP, 512, SMEM_BYTES>>>(hidden, nh1, nw0, w1, w2, logits, T0);
    aggout_kernel<<<400, 256>>>(logits, nh1, agg_a, 3200);
    // hop 1, level 1
    logits_kernel<<<GP, 512, SMEM_BYTES>>>(nh1, nh2, nw1, w1, w2, logits, T1);
    aggout_kernel<<<4800, 256>>>(logits, nh2, agg_b, 38400);
    // hop 2
    logits_kernel<<<GP, 512, SMEM_BYTES>>>(agg_a, agg_b, nw0, w1, w2, logits, T0);
    aggout_kernel<<<400, 256>>>(logits, agg_b, agg_c, 3200);
    // gate
    final_kernel<<<3200, 128>>>(hidden, agg_a, agg_c, w3, w4, sv, out);
}

// round 7
// speedup vs baseline: 3.1862x; 1.3429x over previous
#include <cuda_runtime.h>
#include <cstdint>

#define D 128
#define S 12
#define ITEMS_PER_TILE 20
#define MTILE 240            // 15 m16 row-tiles, exactly 20 items
#define NWARPS 15
#define NTHREADS 480
#define KSTEPS 8             // K=128, 16 per bf16 mma
#define NT 16                // n-tiles of 8 -> N=128
#define LDF 132              // smem row stride (floats)

// ---- scratch (allocation-free rule) ----
__device__ float g_agg_a[3200  * 128];
__device__ float g_agg_b[38400 * 128];
__device__ float g_agg_c[3200  * 128];

// SMEM floats: nb[240*132] + it[20*128] + btab(8*16*32 uint2 = 8192 f) + w1b+w2s + nbws+lgs+alps
#define BTAB_U2   (KSTEPS * NT * 32)
#define SMEM_FLOATS (MTILE * LDF + ITEMS_PER_TILE * D + BTAB_U2 * 2 + 128 + 128 + 3 * MTILE)
#define SMEM_BYTES  (SMEM_FLOATS * 4)

__device__ __forceinline__ uint32_t bf16x2(float lo, float hi) {
    uint32_t r;
    asm("cvt.rn.bf16x2.f32 %0, %1, %2;" : "=r"(r) : "f"(hi), "f"(lo));
    return r;
}
__device__ __forceinline__ void mma_bf16(float* d, uint32_t a0, uint32_t a1,
                                         uint32_t a2, uint32_t a3,
                                         uint32_t b0, uint32_t b1) {
    asm volatile(
        "mma.sync.aligned.m16n8k16.row.col.f32.bf16.bf16.f32 "
        "{%0,%1,%2,%3}, {%4,%5,%6,%7}, {%8,%9}, {%0,%1,%2,%3};"
        : "+f"(d[0]), "+f"(d[1]), "+f"(d[2]), "+f"(d[3])
        : "r"(a0), "r"(a1), "r"(a2), "r"(a3), "r"(b0), "r"(b1));
}
__device__ __forceinline__ float lrelu(float x) { return x > 0.f ? x : 0.2f * x; }

// Fused aggregate: per tile of 20 items (240 rows):
//   logits = lrelu((item (*) nbh | nbw) @ w1) @ w2  -> softmax(12) -> out = sum alpha*nbh
__global__ __launch_bounds__(NTHREADS, 1) void fused_agg_kernel(
    const float* __restrict__ item, const float* __restrict__ nbh,
    const float* __restrict__ nbw,  const float* __restrict__ w1,
    const float* __restrict__ w2,   float* __restrict__ out,
    int ntiles)
{
    extern __shared__ float sm[];
    float* nb   = sm;                             // [240][132] raw neighbor tile
    float* it   = nb + MTILE * LDF;               // [20][128]  item rows
    uint2* btab = (uint2*)(it + ITEMS_PER_TILE * D);  // [8][16][32] bf16x2 pairs
    float* w1b  = (float*)(btab + BTAB_U2);       // [128] bias row w1[128][:]
    float* w2s  = w1b + 128;                      // [128]
    float* nbws = w2s + 128;                      // [240]
    float* lgs  = nbws + MTILE;                   // [240] logits
    float* alps = lgs + MTILE;                    // [240] alphas

    const int tid  = threadIdx.x;
    const int lane = tid & 31;
    const int warp = tid >> 5;
    const int c = lane & 3;
    const int g = lane >> 2;
    const int wrow = warp * 16;

    // ---- one-time: stage w1 as bf16 B-fragment table, bias row, w2 ----
    for (int idx = tid; idx < BTAB_U2; idx += NTHREADS) {
        int t  = idx & 31;
        int j  = (idx >> 5) & 15;
        int ks = idx >> 9;
        int tc = t & 3, tg = t >> 2;
        int k0 = ks * 16 + 2 * tc;
        int n  = j * 8 + tg;
        uint32_t b0 = bf16x2(w1[k0 * D + n],       w1[(k0 + 1) * D + n]);
        uint32_t b1 = bf16x2(w1[(k0 + 8) * D + n], w1[(k0 + 9) * D + n]);
        btab[idx] = make_uint2(b0, b1);
    }
    if (tid < D) { w1b[tid] = w1[D * D + tid]; w2s[tid] = w2[tid]; }
    __syncthreads();

    // per-thread constant row pointers (rows fixed across tiles)
    const int r0 = wrow + g, r1 = wrow + g + 8;
    const float* nbr0 = &nb[r0 * LDF];
    const float* nbr1 = &nb[r1 * LDF];
    const float* itr0 = &it[((unsigned)r0 / 12u) * D];
    const float* itr1 = &it[((unsigned)r1 / 12u) * D];

    for (int tile = blockIdx.x; tile < ntiles; tile += gridDim.x) {
        const int rowbase  = tile * MTILE;
        const int itembase = tile * ITEMS_PER_TILE;

        // ---- stage neighbor tile (240 x 32 float4) ----
        #pragma unroll
        for (int i = 0; i < (MTILE * 32) / NTHREADS; i++) {     // 16 iters
            const int idx = tid + i * NTHREADS;
            const int r = idx >> 5, l4 = idx & 31;
            float4 v = ((const float4*)nbh)[(size_t)(rowbase + r) * 32 + l4];
            *(float4*)&nb[r * LDF + l4 * 4] = v;
        }
        // ---- stage item rows (20 x 32 float4) ----
        {
            const float4* src = (const float4*)(item + (size_t)itembase * D);
            for (int idx = tid; idx < ITEMS_PER_TILE * 32; idx += NTHREADS)
                ((float4*)it)[idx] = src[idx];
        }
        if (tid < MTILE) nbws[tid] = nbw[rowbase + tid];
        __syncthreads();

        // ---- mainloop: one m16 tile per warp, N=128, bf16 k16 ----
        float acc[NT][4];
        #pragma unroll
        for (int j = 0; j < NT; j++)
            #pragma unroll
            for (int q = 0; q < 4; q++) acc[j][q] = 0.f;

        #pragma unroll 1
        for (int ks = 0; ks < KSTEPS; ks++) {
            const int k0 = ks * 16 + 2 * c;
            float2 n00 = *(const float2*)&nbr0[k0];
            float2 n01 = *(const float2*)&nbr0[k0 + 8];
            float2 n10 = *(const float2*)&nbr1[k0];
            float2 n11 = *(const float2*)&nbr1[k0 + 8];
            float2 i00 = *(const float2*)&itr0[k0];
            float2 i01 = *(const float2*)&itr0[k0 + 8];
            float2 i10 = *(const float2*)&itr1[k0];
            float2 i11 = *(const float2*)&itr1[k0 + 8];
            uint32_t a0 = bf16x2(n00.x * i00.x, n00.y * i00.y);
            uint32_t a1 = bf16x2(n10.x * i10.x, n10.y * i10.y);
            uint32_t a2 = bf16x2(n01.x * i01.x, n01.y * i01.y);
            uint32_t a3 = bf16x2(n11.x * i11.x, n11.y * i11.y);
            const uint2* bks = &btab[ks * NT * 32];
            #pragma unroll
            for (int j = 0; j < NT; j++) {
                uint2 b = bks[j * 32 + lane];
                mma_bf16(acc[j], a0, a1, a2, a3, b.x, b.y);
            }
        }

        // ---- logits: bias term, lrelu, dot w2, reduce over c ----
        {
            const float nbw0 = nbws[r0];
            const float nbw1 = nbws[r1];
            float l0 = 0.f, l1 = 0.f;
            #pragma unroll
            for (int j = 0; j < NT; j++) {
                float2 wb = *(const float2*)&w1b[j * 8 + 2 * c];
                float2 wv = *(const float2*)&w2s[j * 8 + 2 * c];
                float v0 = fmaf(nbw0, wb.x, acc[j][0]);
                float v1 = fmaf(nbw0, wb.y, acc[j][1]);
                float v2 = fmaf(nbw1, wb.x, acc[j][2]);
                float v3 = fmaf(nbw1, wb.y, acc[j][3]);
                l0 = fmaf(lrelu(v0), wv.x, l0);
                l0 = fmaf(lrelu(v1), wv.y, l0);
                l1 = fmaf(lrelu(v2), wv.x, l1);
                l1 = fmaf(lrelu(v3), wv.y, l1);
            }
            l0 += __shfl_xor_sync(0xffffffffu, l0, 1);
            l0 += __shfl_xor_sync(0xffffffffu, l0, 2);
            l1 += __shfl_xor_sync(0xffffffffu, l1, 1);
            l1 += __shfl_xor_sync(0xffffffffu, l1, 2);
            if (c == 0) { lgs[r0] = l0; lgs[r1] = l1; }
        }
        __syncthreads();

        // ---- softmax per item (20 parallel threads) ----
        if (tid < ITEMS_PER_TILE) {
            const int base = tid * S;
            float m = lgs[base];
            #pragma unroll
            for (int s = 1; s < S; s++) m = fmaxf(m, lgs[base + s]);
            float e[S]; float sum = 0.f;
            #pragma unroll
            for (int s = 0; s < S; s++) { e[s] = __expf(lgs[base + s] - m); sum += e[s]; }
            const float inv = 1.f / sum;
            #pragma unroll
            for (int s = 0; s < S; s++) alps[base + s] = e[s] * inv;
        }
        __syncthreads();

        // ---- weighted neighbor sum from SMEM tile ----
        for (int idx = tid; idx < ITEMS_PER_TILE * 32; idx += NTHREADS) {
            const int i = idx >> 5, l4 = idx & 31;
            const float* al  = &alps[i * S];
            const float* nbp = &nb[(i * S) * LDF + l4 * 4];
            float4 o = make_float4(0.f, 0.f, 0.f, 0.f);
            #pragma unroll
            for (int s = 0; s < S; s++) {
                float4 v = *(const float4*)&nbp[s * LDF];
                const float a = al[s];
                o.x = fmaf(a, v.x, o.x); o.y = fmaf(a, v.y, o.y);
                o.z = fmaf(a, v.z, o.z); o.w = fmaf(a, v.w, o.w);
            }
            *(float4*)&out[(size_t)(itembase + i) * D + l4 * 4] = o;
        }
        __syncthreads();   // smem reused next tile
    }
}

// ---- final gating (block per item; FFMA2-packed dual GEMV) ----
#define FMA2(acc, a, b) \
    asm("fma.rn.f32x2 %0, %1, %2, %0;" : "+l"(acc) : "l"(a), "l"(b))
__device__ __forceinline__ unsigned long long pack_f32(float lo, float hi) {
    unsigned long long p;
    asm("mov.b64 %0, {%1, %2};" : "=l"(p) : "r"(__float_as_uint(lo)), "r"(__float_as_uint(hi)));
    return p;
}
__device__ __forceinline__ void unpack_f32(unsigned long long p, float& lo, float& hi) {
    asm("mov.b64 {%0, %1}, %2;" : "=f"(lo), "=f"(hi) : "l"(p));
}

__global__ __launch_bounds__(128) void final_kernel(
    const float* __restrict__ hidden, const float* __restrict__ agg_a,
    const float* __restrict__ agg_c,  const float* __restrict__ w3,
    const float* __restrict__ w4,     const float* __restrict__ sv,
    float* __restrict__ out)
{
    const int n = blockIdx.x;
    const int t = threadIdx.x;
    __shared__ unsigned long long sh_hg[D];

    const float s0 = sv[0], s1 = sv[1];
    float h = hidden[(size_t)n * D + t];
    float g = s0 * agg_a[(size_t)n * D + t] + s1 * agg_c[(size_t)n * D + t];
    sh_hg[t] = pack_f32(h, g);
    __syncthreads();

    unsigned long long acc = 0;
    const float* w3c = w3 + t;
    const float* w4c = w4 + t;
    #pragma unroll 4
    for (int k = 0; k < D; k++) {
        unsigned long long wp = pack_f32(__ldg(&w3c[k * D]), __ldg(&w4c[k * D]));
        FMA2(acc, sh_hg[k], wp);
    }
    float a0, a1;
    unpack_f32(acc, a0, a1);
    float wgt = 1.f / (1.f + __expf(-(a0 + a1)));
    out[(size_t)n * D + t] = (1.f - wgt) * h + wgt * g;
}

extern "C" void kernel_launch(void* const* d_in, const int* in_sizes, int n_in,
                              void* d_out, int out_size)
{
    const float* hidden = (const float*)d_in[0];
    const float* nh1    = (const float*)d_in[1];
    const float* nh2    = (const float*)d_in[2];
    const float* nw0    = (const float*)d_in[3];
    const float* nw1    = (const float*)d_in[4];
    const float* w1     = (const float*)d_in[5];
    const float* w2     = (const float*)d_in[6];
    const float* w3     = (const float*)d_in[7];
    const float* w4     = (const float*)d_in[8];
    const float* sv     = (const float*)d_in[9];
    float* out = (float*)d_out;

    float *agg_a, *agg_b, *agg_c;
    cudaGetSymbolAddress((void**)&agg_a, g_agg_a);
    cudaGetSymbolAddress((void**)&agg_b, g_agg_b);
    cudaGetSymbolAddress((void**)&agg_c, g_agg_c);

    cudaFuncSetAttribute(fused_agg_kernel,
                         cudaFuncAttributeMaxDynamicSharedMemorySize, SMEM_BYTES);

    const int GP = 148;
    const int T0 = 3200  / ITEMS_PER_TILE;   // 160 tiles
    const int T1 = 38400 / ITEMS_PER_TILE;   // 1920 tiles

    // hop 1
    fused_agg_kernel<<<GP, NTHREADS, SMEM_BYTES>>>(hidden, nh1, nw0, w1, w2, agg_a, T0);
    fused_agg_kernel<<<GP, NTHREADS, SMEM_BYTES>>>(nh1,    nh2, nw1, w1, w2, agg_b, T1);
    // hop 2
    fused_agg_kernel<<<GP, NTHREADS, SMEM_BYTES>>>(agg_a,  agg_b, nw0, w1, w2, agg_c, T0);
    // gate
    final_kernel<<<3200, 128>>>(hidden, agg_a, agg_c, w3, w4, sv, out);
}

// round 8
// speedup vs baseline: 3.5388x; 1.1107x over previous
#include <cuda_runtime.h>
#include <cstdint>

#define D 128
#define S 12
#define ITEMS_PER_TILE 12
#define MTILE 144            // 9 m16 row-tiles, exactly 12 items
#define NWARPS 9
#define NTHREADS 288
#define KSTEPS 8             // K=128, 16 per bf16 mma
#define NT 16                // n-tiles of 8 -> N=128
#define LDF 132              // smem row stride (floats), 528B rows (16B aligned)

// ---- scratch (allocation-free rule) ----
__device__ float g_agg_a[3200  * 128];
__device__ float g_agg_b[38400 * 128];
__device__ float g_agg_c[3200  * 128];

#define NBSZ   (MTILE * LDF)            // 19008 floats per buffer
#define ITSZ   (ITEMS_PER_TILE * D)     // 1536
#define BTAB_U2 (KSTEPS * NT * 32)      // 4096 uint2
#define SMEM_FLOATS (2 * NBSZ + 2 * ITSZ + BTAB_U2 * 2 + 128 + 128 + 2 * MTILE + 2 * MTILE)
#define SMEM_BYTES  (SMEM_FLOATS * 4)

__device__ __forceinline__ uint32_t bf16x2(float lo, float hi) {
    uint32_t r;
    asm("cvt.rn.bf16x2.f32 %0, %1, %2;" : "=r"(r) : "f"(hi), "f"(lo));
    return r;
}
__device__ __forceinline__ void mma_bf16(float* d, uint32_t a0, uint32_t a1,
                                         uint32_t a2, uint32_t a3,
                                         uint32_t b0, uint32_t b1) {
    asm volatile(
        "mma.sync.aligned.m16n8k16.row.col.f32.bf16.bf16.f32 "
        "{%0,%1,%2,%3}, {%4,%5,%6,%7}, {%8,%9}, {%0,%1,%2,%3};"
        : "+f"(d[0]), "+f"(d[1]), "+f"(d[2]), "+f"(d[3])
        : "r"(a0), "r"(a1), "r"(a2), "r"(a3), "r"(b0), "r"(b1));
}
__device__ __forceinline__ float lrelu(float x) { return x > 0.f ? x : 0.2f * x; }

__device__ __forceinline__ void cp16(uint32_t smem_dst, const void* gsrc) {
    asm volatile("cp.async.cg.shared.global [%0], [%1], 16;" :: "r"(smem_dst), "l"(gsrc));
}
__device__ __forceinline__ void cp_commit() {
    asm volatile("cp.async.commit_group;");
}
__device__ __forceinline__ void cp_wait1() {
    asm volatile("cp.async.wait_group 1;" ::: "memory");
}
__device__ __forceinline__ uint32_t smem_u32(const void* p) {
    return (uint32_t)__cvta_generic_to_shared(p);
}

// Fused aggregate with cp.async double-buffered tile pipeline.
__global__ __launch_bounds__(NTHREADS, 1) void fused_agg_kernel(
    const float* __restrict__ item, const float* __restrict__ nbh,
    const float* __restrict__ nbw,  const float* __restrict__ w1,
    const float* __restrict__ w2,   float* __restrict__ out,
    int ntiles, int nitems)
{
    extern __shared__ float sm[];
    float* nbbuf  = sm;                           // [2][144*132]
    float* itbuf  = nbbuf + 2 * NBSZ;             // [2][12*128]
    uint2* btab   = (uint2*)(itbuf + 2 * ITSZ);   // [8][16][32]
    float* w1b    = (float*)(btab + BTAB_U2);     // [128]
    float* w2s    = w1b + 128;                    // [128]
    float* nbwbuf = w2s + 128;                    // [2][144]
    float* lgs    = nbwbuf + 2 * MTILE;           // [144]
    float* alps   = lgs + MTILE;                  // [144]

    const int tid  = threadIdx.x;
    const int lane = tid & 31;
    const int warp = tid >> 5;
    const int c = lane & 3;
    const int g = lane >> 2;
    const int wrow = warp * 16;
    const int nrows = nitems * S;

    // ---- one-time: w1 bf16 B-fragment table, bias row, w2 ----
    for (int idx = tid; idx < BTAB_U2; idx += NTHREADS) {
        int t  = idx & 31;
        int j  = (idx >> 5) & 15;
        int ks = idx >> 9;
        int tc = t & 3, tg = t >> 2;
        int k0 = ks * 16 + 2 * tc;
        int n  = j * 8 + tg;
        uint32_t b0 = bf16x2(w1[k0 * D + n],       w1[(k0 + 1) * D + n]);
        uint32_t b1 = bf16x2(w1[(k0 + 8) * D + n], w1[(k0 + 9) * D + n]);
        btab[idx] = make_uint2(b0, b1);
    }
    if (tid < D) { w1b[tid] = w1[D * D + tid]; w2s[tid] = w2[tid]; }
    __syncthreads();

    // ---- prefetch helper (lambda-free, inline) ----
    // nb: 144 rows x 32 float4 = 4608 f4 -> 16 per thread
    // it: 12 rows x 32 f4 = 384 -> <=2 per thread
    // nbw: 36 f4 -> tid < 36
    #define PREFETCH(TILE, PB) do {                                                   \
        const int _rb = (TILE) * MTILE;                                               \
        const int _ib = (TILE) * ITEMS_PER_TILE;                                      \
        float* _nbd = nbbuf + (PB) * NBSZ;                                            \
        _Pragma("unroll")                                                             \
        for (int _i = 0; _i < 16; _i++) {                                             \
            const int _idx = tid + _i * NTHREADS;                                     \
            const int _r = _idx >> 5, _l4 = _idx & 31;                                \
            const long _Rc = min(_rb + _r, nrows - 1);                                \
            cp16(smem_u32(&_nbd[_r * LDF + _l4 * 4]),                                 \
                 (const float4*)nbh + _Rc * 32 + _l4);                                \
        }                                                                             \
        float* _itd = itbuf + (PB) * ITSZ;                                            \
        _Pragma("unroll")                                                             \
        for (int _i = 0; _i < 2; _i++) {                                              \
            const int _idx = tid + _i * NTHREADS;                                     \
            if (_idx < ITEMS_PER_TILE * 32) {                                         \
                const int _r = _idx >> 5, _l4 = _idx & 31;                            \
                const long _Ic = min(_ib + _r, nitems - 1);                           \
                cp16(smem_u32(&_itd[_r * D + _l4 * 4]),                               \
                     (const float4*)item + _Ic * 32 + _l4);                           \
            }                                                                         \
        }                                                                             \
        if (tid < MTILE / 4) {                                                        \
            const long _Wc = min((TILE) * (MTILE / 4) + tid, nrows / 4 - 1);          \
            cp16(smem_u32(&nbwbuf[(PB) * MTILE + tid * 4]),                           \
                 (const float4*)nbw + _Wc);                                           \
        }                                                                             \
    } while (0)

    // ---- pipeline prologue ----
    int pb = 0;
    if (blockIdx.x < ntiles) PREFETCH(blockIdx.x, 0);
    cp_commit();

    for (int tile = blockIdx.x; tile < ntiles; tile += gridDim.x) {
        const int itembase = tile * ITEMS_PER_TILE;
        const int nxt = tile + gridDim.x;
        if (nxt < ntiles) PREFETCH(nxt, pb ^ 1);
        cp_commit();
        cp_wait1();          // current tile's group complete
        __syncthreads();

        const float* nb = nbbuf + pb * NBSZ;
        const float* it = itbuf + pb * ITSZ;
        const float* nbws = nbwbuf + pb * MTILE;

        const int r0 = wrow + g, r1 = r0 + 8;
        const float* nbr0 = &nb[r0 * LDF];
        const float* nbr1 = &nb[r1 * LDF];
        const float* itr0 = &it[((unsigned)r0 / 12u) * D];
        const float* itr1 = &it[((unsigned)r1 / 12u) * D];

        // ---- mainloop: one m16 tile per warp, N=128, bf16 k16 ----
        float acc[NT][4];
        #pragma unroll
        for (int j = 0; j < NT; j++)
            #pragma unroll
            for (int q = 0; q < 4; q++) acc[j][q] = 0.f;

        #pragma unroll 1
        for (int ks = 0; ks < KSTEPS; ks++) {
            const int k0 = ks * 16 + 2 * c;
            float2 n00 = *(const float2*)&nbr0[k0];
            float2 n01 = *(const float2*)&nbr0[k0 + 8];
            float2 n10 = *(const float2*)&nbr1[k0];
            float2 n11 = *(const float2*)&nbr1[k0 + 8];
            float2 i00 = *(const float2*)&itr0[k0];
            float2 i01 = *(const float2*)&itr0[k0 + 8];
            float2 i10 = *(const float2*)&itr1[k0];
            float2 i11 = *(const float2*)&itr1[k0 + 8];
            uint32_t a0 = bf16x2(n00.x * i00.x, n00.y * i00.y);
            uint32_t a1 = bf16x2(n10.x * i10.x, n10.y * i10.y);
            uint32_t a2 = bf16x2(n01.x * i01.x, n01.y * i01.y);
            uint32_t a3 = bf16x2(n11.x * i11.x, n11.y * i11.y);
            const uint2* bks = &btab[ks * NT * 32];
            #pragma unroll
            for (int j = 0; j < NT; j++) {
                uint2 b = bks[j * 32 + lane];
                mma_bf16(acc[j], a0, a1, a2, a3, b.x, b.y);
            }
        }

        // ---- logits: bias term, lrelu, dot w2, reduce over c ----
        {
            const float nbw0 = nbws[r0];
            const float nbw1 = nbws[r1];
            float l0 = 0.f, l1 = 0.f;
            #pragma unroll
            for (int j = 0; j < NT; j++) {
                float2 wb = *(const float2*)&w1b[j * 8 + 2 * c];
                float2 wv = *(const float2*)&w2s[j * 8 + 2 * c];
                float v0 = fmaf(nbw0, wb.x, acc[j][0]);
                float v1 = fmaf(nbw0, wb.y, acc[j][1]);
                float v2 = fmaf(nbw1, wb.x, acc[j][2]);
                float v3 = fmaf(nbw1, wb.y, acc[j][3]);
                l0 = fmaf(lrelu(v0), wv.x, l0);
                l0 = fmaf(lrelu(v1), wv.y, l0);
                l1 = fmaf(lrelu(v2), wv.x, l1);
                l1 = fmaf(lrelu(v3), wv.y, l1);
            }
            l0 += __shfl_xor_sync(0xffffffffu, l0, 1);
            l0 += __shfl_xor_sync(0xffffffffu, l0, 2);
            l1 += __shfl_xor_sync(0xffffffffu, l1, 1);
            l1 += __shfl_xor_sync(0xffffffffu, l1, 2);
            if (c == 0) { lgs[r0] = l0; lgs[r1] = l1; }
        }
        __syncthreads();

        // ---- softmax per item ----
        if (tid < ITEMS_PER_TILE) {
            const int base = tid * S;
            float m = lgs[base];
            #pragma unroll
            for (int s = 1; s < S; s++) m = fmaxf(m, lgs[base + s]);
            float e[S]; float sum = 0.f;
            #pragma unroll
            for (int s = 0; s < S; s++) { e[s] = __expf(lgs[base + s] - m); sum += e[s]; }
            const float inv = 1.f / sum;
            #pragma unroll
            for (int s = 0; s < S; s++) alps[base + s] = e[s] * inv;
        }
        __syncthreads();

        // ---- weighted neighbor sum from SMEM tile (guarded stores) ----
        for (int idx = tid; idx < ITEMS_PER_TILE * 32; idx += NTHREADS) {
            const int i = idx >> 5, l4 = idx & 31;
            if (itembase + i >= nitems) break;
            const float* al  = &alps[i * S];
            const float* nbp = &nb[(i * S) * LDF + l4 * 4];
            float4 o = make_float4(0.f, 0.f, 0.f, 0.f);
            #pragma unroll
            for (int s = 0; s < S; s++) {
                float4 v = *(const float4*)&nbp[s * LDF];
                const float a = al[s];
                o.x = fmaf(a, v.x, o.x); o.y = fmaf(a, v.y, o.y);
                o.z = fmaf(a, v.z, o.z); o.w = fmaf(a, v.w, o.w);
            }
            *(float4*)&out[(size_t)(itembase + i) * D + l4 * 4] = o;
        }
        __syncthreads();   // protect buffers before next iteration's prefetch
        pb ^= 1;
    }
}

// ---- final gating: 8 items per block; amortize w3/w4 reads ----
#define FMA2(acc, a, b) \
    asm("fma.rn.f32x2 %0, %1, %2, %0;" : "+l"(acc) : "l"(a), "l"(b))
__device__ __forceinline__ unsigned long long pack_f32(float lo, float hi) {
    unsigned long long p;
    asm("mov.b64 %0, {%1, %2};" : "=l"(p) : "r"(__float_as_uint(lo)), "r"(__float_as_uint(hi)));
    return p;
}
__device__ __forceinline__ void unpack_f32(unsigned long long p, float& lo, float& hi) {
    asm("mov.b64 {%0, %1}, %2;" : "=f"(lo), "=f"(hi) : "l"(p));
}

__global__ __launch_bounds__(128) void final_kernel(
    const float* __restrict__ hidden, const float* __restrict__ agg_a,
    const float* __restrict__ agg_c,  const float* __restrict__ w3,
    const float* __restrict__ w4,     const float* __restrict__ sv,
    float* __restrict__ out)
{
    const int nbase = blockIdx.x * 8;
    const int t = threadIdx.x;
    __shared__ unsigned long long sh_hg[8][D];

    const float s0 = sv[0], s1 = sv[1];
    float h[8], g[8];
    #pragma unroll
    for (int i = 0; i < 8; i++) {
        const size_t off = (size_t)(nbase + i) * D + t;
        h[i] = hidden[off];
        g[i] = s0 * agg_a[off] + s1 * agg_c[off];
        sh_hg[i][t] = pack_f32(h[i], g[i]);
    }
    __syncthreads();

    unsigned long long acc[8];
    #pragma unroll
    for (int i = 0; i < 8; i++) acc[i] = 0ULL;

    const float* w3c = w3 + t;
    const float* w4c = w4 + t;
    #pragma unroll 2
    for (int k = 0; k < D; k++) {
        unsigned long long wp = pack_f32(__ldg(&w3c[k * D]), __ldg(&w4c[k * D]));
        #pragma unroll
        for (int i = 0; i < 8; i++) FMA2(acc[i], sh_hg[i][k], wp);
    }
    #pragma unroll
    for (int i = 0; i < 8; i++) {
        float a0, a1;
        unpack_f32(acc[i], a0, a1);
        const float wgt = 1.f / (1.f + __expf(-(a0 + a1)));
        out[(size_t)(nbase + i) * D + t] = (1.f - wgt) * h[i] + wgt * g[i];
    }
}

extern "C" void kernel_launch(void* const* d_in, const int* in_sizes, int n_in,
                              void* d_out, int out_size)
{
    const float* hidden = (const float*)d_in[0];
    const float* nh1    = (const float*)d_in[1];
    const float* nh2    = (const float*)d_in[2];
    const float* nw0    = (const float*)d_in[3];
    const float* nw1    = (const float*)d_in[4];
    const float* w1     = (const float*)d_in[5];
    const float* w2     = (const float*)d_in[6];
    const float* w3     = (const float*)d_in[7];
    const float* w4     = (const float*)d_in[8];
    const float* sv     = (const float*)d_in[9];
    float* out = (float*)d_out;

    float *agg_a, *agg_b, *agg_c;
    cudaGetSymbolAddress((void**)&agg_a, g_agg_a);
    cudaGetSymbolAddress((void**)&agg_b, g_agg_b);
    cudaGetSymbolAddress((void**)&agg_c, g_agg_c);

    cudaFuncSetAttribute(fused_agg_kernel,
                         cudaFuncAttributeMaxDynamicSharedMemorySize, SMEM_BYTES);

    const int GP = 148;
    const int T0 = (3200  + ITEMS_PER_TILE - 1) / ITEMS_PER_TILE;   // 267
    const int T1 = 38400 / ITEMS_PER_TILE;                          // 3200

    // hop 1
    fused_agg_kernel<<<GP, NTHREADS, SMEM_BYTES>>>(hidden, nh1, nw0, w1, w2, agg_a, T0, 3200);
    fused_agg_kernel<<<GP, NTHREADS, SMEM_BYTES>>>(nh1,    nh2, nw1, w1, w2, agg_b, T1, 38400);
    // hop 2
    fused_agg_kernel<<<GP, NTHREADS, SMEM_BYTES>>>(agg_a,  agg_b, nw0, w1, w2, agg_c, T0, 3200);
    // gate
    final_kernel<<<400, 128>>>(hidden, agg_a, agg_c, w3, w4, sv, out);
}